// round 15
// baseline (speedup 1.0000x reference)
#include <cuda_runtime.h>
#include <cuda_bf16.h>
#include <cuda_fp16.h>
#include <math.h>
#include <stdint.h>

// MMD via fp8(e4m3) mma.sync Gram, f16 accumulators.
// R15: occupancy gradient, step 3. occ 22->37->50% mapped pair 59.8->50.5->44.4us.
// Now __launch_bounds__(256,5) (51-reg cap -> 40 warps/SM). Epilogue screen
// uses TILE-LEVEL min norms (smem) so the hot path needs no per-thread sq regs.
// exp(-d2/2) underflows to 0 in fp32 for d2>174.67; min off-diagonal d2 ~200,
// so fragments are screened; diagonal emitted analytically (exactly 1.0).

#define NROW 4096
#define DIM  192
#define ZROW 8192
#define TMR  128                   // tile rows
#define TMC  64                    // tile cols
#define NTB  64                    // row tiles (8192/128)
#define NTILE 4160                 // sum_{bi}(128-2bi) = 64*65
#define NKS  6                     // K steps of 32 fp8

#define RSTRIDE 208                // 192B row + 16B pad (conflict-free ldmatrix)
#define OFF_A   0
#define OFF_B   (TMR * RSTRIDE)            // 26624
#define OFF_SQI (OFF_B + TMC * RSTRIDE)    // 39936 (128 floats)
#define OFF_SQJ (OFF_SQI + 512)            // (64 floats)
#define OFF_RED (OFF_SQJ + 256)            // [0..7]=warp sums, [8]=minI, [9]=minJ
#define SMEM_TOTAL (OFF_RED + 64)

__device__ double  g_sums[3];               // XX, XY, YY weighted sums
__device__ float   g_sq[ZROW];              // fp32 squared norms
__device__ uint8_t g_zb[ZROW * DIM];        // e4m3 copy of Z

__device__ __forceinline__ uint32_t smem_u32(const void* p) {
    return (uint32_t)__cvta_generic_to_shared((void*)p);
}

#define LDSM4(r, addr)                                                         \
    asm volatile("ldmatrix.sync.aligned.m8n8.x4.shared.b16 "                   \
                 "{%0, %1, %2, %3}, [%4];"                                     \
                 : "=r"((r)[0]), "=r"((r)[1]), "=r"((r)[2]), "=r"((r)[3])      \
                 : "r"(addr))

#define MMAF8H(c, a, b0, b1)                                                   \
    asm volatile("mma.sync.aligned.m16n8k32.row.col.f16.e4m3.e4m3.f16 "        \
                 "{%0, %1}, {%2, %3, %4, %5}, {%6, %7}, {%0, %1};"             \
                 : "+r"((c)[0]), "+r"((c)[1])                                  \
                 : "r"((a)[0]), "r"((a)[1]), "r"((a)[2]), "r"((a)[3]),         \
                   "r"(b0), "r"(b1))

#define CPASYNC16(dst, src)                                                    \
    asm volatile("cp.async.cg.shared.global [%0], [%1], 16;"                   \
                 :: "r"(dst), "l"(src))

// ---------------------------------------------------------------------------
// prep: sixteenth-row per thread (3 independent float4 loads), 1024 CTAs x 128
// ---------------------------------------------------------------------------
__global__ void __launch_bounds__(128) prep_kernel(const float* __restrict__ x,
                                                   const float* __restrict__ y) {
    if (blockIdx.x == 0 && threadIdx.x < 3) g_sums[threadIdx.x] = 0.0;
    const int gid  = blockIdx.x * 128 + threadIdx.x;   // 131072 threads
    const int row  = gid >> 4;
    const int part = gid & 15;                         // 12 floats each
    const float* p = ((row < NROW) ? (x + (size_t)row * DIM)
                                   : (y + (size_t)(row - NROW) * DIM)) + part * 12;

    float4 v[3];
    #pragma unroll
    for (int i = 0; i < 3; i++) v[i] = *(const float4*)(p + i * 4);

    float s = 0.f;
    uint32_t pk[3];
    #pragma unroll
    for (int i = 0; i < 3; i++) {
        s = fmaf(v[i].x, v[i].x, s); s = fmaf(v[i].y, v[i].y, s);
        s = fmaf(v[i].z, v[i].z, s); s = fmaf(v[i].w, v[i].w, s);
        unsigned short lo, hi;
        asm("cvt.rn.satfinite.e4m3x2.f32 %0, %1, %2;" : "=h"(lo) : "f"(v[i].y), "f"(v[i].x));
        asm("cvt.rn.satfinite.e4m3x2.f32 %0, %1, %2;" : "=h"(hi) : "f"(v[i].w), "f"(v[i].z));
        pk[i] = (uint32_t)lo | ((uint32_t)hi << 16);
    }
    uint8_t* dst = g_zb + (size_t)row * DIM + part * 12;   // 4B aligned
    #pragma unroll
    for (int i = 0; i < 3; i++)
        *(uint32_t*)(dst + i * 4) = pk[i];

    s += __shfl_xor_sync(0xffffffffu, s, 1);
    s += __shfl_xor_sync(0xffffffffu, s, 2);
    s += __shfl_xor_sync(0xffffffffu, s, 4);
    s += __shfl_xor_sync(0xffffffffu, s, 8);
    if (part == 0) g_sq[row] = s;
}

// ---------------------------------------------------------------------------
// pair kernel: 128x64 tile per 256-thread CTA, 8 warps (4x2), each warp
// 32x32 via m16n8k32 e4m3/f16 MMA. Compact 1-D triangular grid. 51-reg cap.
// ---------------------------------------------------------------------------
__global__ void __launch_bounds__(256, 5) pair_kernel() {
    extern __shared__ char smem[];
    const uint32_t sbase = smem_u32(smem);

    // decode t -> (bi, cj): tiles for row bi start at S(bi) = bi*(129-bi)
    const int t = blockIdx.x;
    int bi = (int)((129.0 - sqrt(16641.0 - 4.0 * (double)t)) * 0.5);
    if (bi < 0) bi = 0;
    if (bi > NTB - 1) bi = NTB - 1;
    while ((bi + 1) * (129 - (bi + 1)) <= t) bi++;
    while (bi * (129 - bi) > t) bi--;
    const int cj = 2 * bi + (t - bi * (129 - bi));
    const bool diag = ((cj >> 1) == bi);   // tile contains diagonal cells

    const int tid  = threadIdx.x;
    const int lane = tid & 31;
    const int wid  = tid >> 5;
    const int wm   = wid >> 1;   // 0..3 : 32-row slab
    const int wn   = wid & 1;    // 0..1 : 32-col slab

    // ---- stage via cp.async (incremental index math) ----
    const uint8_t* Asrc = g_zb + (size_t)bi * TMR * DIM;
    const uint8_t* Bsrc = g_zb + (size_t)cj * TMC * DIM;
    {
        int m = tid / 12, ch = tid - m * 12;   // idx = tid
        int m2 = m, ch2 = ch;
        #pragma unroll
        for (int r = 0; r < 6; r++) {          // A: 1536 chunks
            CPASYNC16(sbase + OFF_A + m * RSTRIDE + ch * 16,
                      Asrc + (size_t)m * DIM + ch * 16);
            m += 21; ch += 4;                  // += 256 = 21*12 + 4
            if (ch >= 12) { ch -= 12; m += 1; }
        }
        if (!diag) {
            #pragma unroll
            for (int r = 0; r < 3; r++) {      // B: 768 chunks
                CPASYNC16(sbase + OFF_B + m2 * RSTRIDE + ch2 * 16,
                          Bsrc + (size_t)m2 * DIM + ch2 * 16);
                m2 += 21; ch2 += 4;
                if (ch2 >= 12) { ch2 -= 12; m2 += 1; }
            }
        }
    }
    asm volatile("cp.async.commit_group;" ::: "memory");
    if (tid < TMR) ((float*)(smem + OFF_SQI))[tid] = g_sq[bi * TMR + tid];
    else if (tid < TMR + TMC)
        ((float*)(smem + OFF_SQJ))[tid - TMR] = g_sq[cj * TMC + tid - TMR];
    asm volatile("cp.async.wait_group 0;" ::: "memory");
    __syncthreads();

    // tile-level min norms for the screen (warps 0/1); visible after 2nd bar
    {
        float* red = (float*)(smem + OFF_RED);
        const float* sqi = (const float*)(smem + OFF_SQI);
        const float* sqj = (const float*)(smem + OFF_SQJ);
        if (wid == 0) {
            float v = fminf(fminf(sqi[lane], sqi[lane + 32]),
                            fminf(sqi[lane + 64], sqi[lane + 96]));
            #pragma unroll
            for (int o = 16; o; o >>= 1) v = fminf(v, __shfl_xor_sync(0xffffffffu, v, o));
            if (lane == 0) red[8] = v;
        } else if (wid == 1) {
            float v = fminf(sqj[lane], sqj[lane + 32]);
            #pragma unroll
            for (int o = 16; o; o >>= 1) v = fminf(v, __shfl_xor_sync(0xffffffffu, v, o));
            if (lane == 0) red[9] = v;
        }
    }

    // per-lane ldmatrix bases
    const uint32_t aBase = sbase + OFF_A
        + (uint32_t)(wm * 32 + (lane & 15)) * RSTRIDE + ((lane >> 4) << 4);
    const uint32_t bOff = diag ? (OFF_A + (uint32_t)(cj & 1) * 64 * RSTRIDE) : OFF_B;
    const uint32_t bBase = sbase + bOff
        + (uint32_t)(wn * 32 + ((lane & 7) | ((lane >> 4) << 3))) * RSTRIDE
        + (((lane >> 3) & 1) << 4);

    uint32_t acc[2][4][2];   // [mt][ntk][row-half], f16x2 each (16 regs)
    #pragma unroll
    for (int i = 0; i < 2; i++)
        #pragma unroll
        for (int j = 0; j < 4; j++) { acc[i][j][0] = 0u; acc[i][j][1] = 0u; }

    #pragma unroll
    for (int ks = 0; ks < NKS; ks++) {
        uint32_t a[2][4], b[2][4];
        #pragma unroll
        for (int mt = 0; mt < 2; mt++)
            LDSM4(a[mt], aBase + (uint32_t)(mt * 16) * RSTRIDE + ks * 32);
        #pragma unroll
        for (int n2 = 0; n2 < 2; n2++)
            LDSM4(b[n2], bBase + (uint32_t)(n2 * 16) * RSTRIDE + ks * 32);
        #pragma unroll
        for (int mt = 0; mt < 2; mt++)
            #pragma unroll
            for (int ntk = 0; ntk < 4; ntk++) {
                const uint32_t* bf = b[ntk >> 1];
                if (ntk & 1) MMAF8H(acc[mt][ntk], a[mt], bf[2], bf[3]);
                else         MMAF8H(acc[mt][ntk], a[mt], bf[0], bf[1]);
            }
    }
    __syncthreads();   // mins visible; smem tiles no longer needed by others

    // ---- epilogue: tile-min screen (HMAX2), then (rarely) exp ----
    float* red = (float*)(smem + OFF_RED);
    const int cls = (cj < 64) ? 0 : ((bi >= 32) ? 2 : 1);   // 0=XX,1=XY,2=YY
    const float wgt = (cls == 1) ? 1.f : 2.f;

    __half2 hm = *(const __half2*)&acc[0][0][0];
    #pragma unroll
    for (int mt = 0; mt < 2; mt++)
        #pragma unroll
        for (int ntk = 0; ntk < 4; ntk++)
            #pragma unroll
            for (int rh = 0; rh < 2; rh++)
                hm = __hmax2(hm, *(const __half2*)&acc[mt][ntk][rh]);
    float accmax = fmaxf(__low2float(hm), __high2float(hm));
    const bool hot = (2.f * accmax - red[8] - red[9]) > -215.f;

    float sum = 0.f;
    if (__ballot_sync(0xffffffffu, hot)) {
        const float* sqi = (const float*)(smem + OFF_SQI);
        const float* sqj = (const float*)(smem + OFF_SQJ);
        const int g  = lane >> 2;
        const int t4 = lane & 3;
        #pragma unroll
        for (int mt = 0; mt < 2; mt++) {
            #pragma unroll
            for (int ntk = 0; ntk < 4; ntk++) {
                #pragma unroll
                for (int rh = 0; rh < 2; rh++) {
                    float2 v2 = __half22float2(*(const __half2*)&acc[mt][ntk][rh]);
                    float siv = sqi[wm * 32 + mt * 16 + g + rh * 8];
                    #pragma unroll
                    for (int cl = 0; cl < 2; cl++) {
                        const int gi = bi * TMR + wm * 32 + mt * 16 + g + rh * 8;
                        const int gj = cj * TMC + wn * 32 + ntk * 8 + 2 * t4 + cl;
                        float sjv = sqj[wn * 32 + ntk * 8 + 2 * t4 + cl];
                        float vv = cl ? v2.y : v2.x;
                        float d2 = fmaxf(siv + sjv - 2.f * vv, 0.f);
                        if (diag && gi >= gj) continue;   // diagonal analytic
                        if (d2 < 174.f) sum += wgt * __expf(-0.5f * d2);
                    }
                }
            }
        }
    }
    if (diag && tid == 0) sum += 64.f;   // exact diagonal cells in this tile

    #pragma unroll
    for (int o = 16; o; o >>= 1) sum += __shfl_xor_sync(0xffffffffu, sum, o);
    if (lane == 0) red[wid] = sum;
    __syncthreads();
    if (tid == 0) {
        float tot = 0.f;
        #pragma unroll
        for (int w = 0; w < 8; w++) tot += red[w];
        atomicAdd(&g_sums[cls], (double)tot);
    }
}

// ---------------------------------------------------------------------------
// finalize
// ---------------------------------------------------------------------------
__global__ void fin_kernel(const float* __restrict__ avg_step,
                           float* __restrict__ out, int out_size) {
    const double inv = 1.0 / ((double)NROW * (double)NROW);
    float xx = (float)(g_sums[0] * inv);
    float xy = (float)(g_sums[1] * inv);
    float yy = (float)(g_sums[2] * inv);
    float mmd  = xx + yy - 2.0f * xy;
    float a    = avg_step[0];
    float loss = mmd + (fmaxf(1.0f, a) - 1.0f) * 0.002f;
    out[0] = loss;
    if (out_size > 1) out[1] = mmd;
}

extern "C" void kernel_launch(void* const* d_in, const int* in_sizes, int n_in,
                              void* d_out, int out_size) {
    const float* x  = (const float*)d_in[0];
    const float* y  = (const float*)d_in[1];
    const float* av = (const float*)d_in[2];
    float* out = (float*)d_out;

    prep_kernel<<<1024, 128>>>(x, y);
    cudaFuncSetAttribute(pair_kernel,
                         cudaFuncAttributeMaxDynamicSharedMemorySize, SMEM_TOTAL);
    pair_kernel<<<NTILE, 256, SMEM_TOTAL>>>();
    fin_kernel<<<1, 1>>>(av, out, out_size);
}

// round 16
// speedup vs baseline: 1.0416x; 1.0416x over previous
#include <cuda_runtime.h>
#include <cuda_bf16.h>
#include <cuda_fp16.h>
#include <math.h>
#include <stdint.h>

// MMD via fp8(e4m3) mma.sync Gram, f16 accumulators.
// R16: occ-5 retry with a genuinely slim register profile (R15's forced
// 51-reg cap spilled): float tri-decode, no sq smem staging (tile-min screen
// from 6 __ldg + warp reduce, written before the single existing barrier),
// per-element sq reads only in the rare hot branch. smem 40KB -> 5 CTAs/SM.
// exp(-d2/2) underflows to 0 in fp32 for d2>174.67; min off-diagonal d2 ~200,
// so fragments are screened; diagonal emitted analytically (exactly 1.0).

#define NROW 4096
#define DIM  192
#define ZROW 8192
#define TMR  128                   // tile rows
#define TMC  64                    // tile cols
#define NTB  64                    // row tiles (8192/128)
#define NTILE 4160                 // sum_{bi}(128-2bi) = 64*65
#define NKS  6                     // K steps of 32 fp8

#define RSTRIDE 208                // 192B row + 16B pad (conflict-free ldmatrix)
#define OFF_A   0
#define OFF_B   (TMR * RSTRIDE)            // 26624
#define OFF_RED (OFF_B + TMC * RSTRIDE)    // 39936: [0..7] warp sums, [8] minI, [9] minJ
#define SMEM_TOTAL (OFF_RED + 64)          // 40000

__device__ double  g_sums[3];               // XX, XY, YY weighted sums
__device__ float   g_sq[ZROW];              // fp32 squared norms
__device__ uint8_t g_zb[ZROW * DIM];        // e4m3 copy of Z

__device__ __forceinline__ uint32_t smem_u32(const void* p) {
    return (uint32_t)__cvta_generic_to_shared((void*)p);
}

#define LDSM4(r, addr)                                                         \
    asm volatile("ldmatrix.sync.aligned.m8n8.x4.shared.b16 "                   \
                 "{%0, %1, %2, %3}, [%4];"                                     \
                 : "=r"((r)[0]), "=r"((r)[1]), "=r"((r)[2]), "=r"((r)[3])      \
                 : "r"(addr))

#define MMAF8H(c, a, b0, b1)                                                   \
    asm volatile("mma.sync.aligned.m16n8k32.row.col.f16.e4m3.e4m3.f16 "        \
                 "{%0, %1}, {%2, %3, %4, %5}, {%6, %7}, {%0, %1};"             \
                 : "+r"((c)[0]), "+r"((c)[1])                                  \
                 : "r"((a)[0]), "r"((a)[1]), "r"((a)[2]), "r"((a)[3]),         \
                   "r"(b0), "r"(b1))

#define CPASYNC16(dst, src)                                                    \
    asm volatile("cp.async.cg.shared.global [%0], [%1], 16;"                   \
                 :: "r"(dst), "l"(src))

// ---------------------------------------------------------------------------
// prep: sixteenth-row per thread (3 independent float4 loads), 1024 CTAs x 128
// ---------------------------------------------------------------------------
__global__ void __launch_bounds__(128) prep_kernel(const float* __restrict__ x,
                                                   const float* __restrict__ y) {
    if (blockIdx.x == 0 && threadIdx.x < 3) g_sums[threadIdx.x] = 0.0;
    const int gid  = blockIdx.x * 128 + threadIdx.x;   // 131072 threads
    const int row  = gid >> 4;
    const int part = gid & 15;                         // 12 floats each
    const float* p = ((row < NROW) ? (x + (size_t)row * DIM)
                                   : (y + (size_t)(row - NROW) * DIM)) + part * 12;

    float4 v[3];
    #pragma unroll
    for (int i = 0; i < 3; i++) v[i] = *(const float4*)(p + i * 4);

    float s = 0.f;
    uint32_t pk[3];
    #pragma unroll
    for (int i = 0; i < 3; i++) {
        s = fmaf(v[i].x, v[i].x, s); s = fmaf(v[i].y, v[i].y, s);
        s = fmaf(v[i].z, v[i].z, s); s = fmaf(v[i].w, v[i].w, s);
        unsigned short lo, hi;
        asm("cvt.rn.satfinite.e4m3x2.f32 %0, %1, %2;" : "=h"(lo) : "f"(v[i].y), "f"(v[i].x));
        asm("cvt.rn.satfinite.e4m3x2.f32 %0, %1, %2;" : "=h"(hi) : "f"(v[i].w), "f"(v[i].z));
        pk[i] = (uint32_t)lo | ((uint32_t)hi << 16);
    }
    uint8_t* dst = g_zb + (size_t)row * DIM + part * 12;   // 4B aligned
    #pragma unroll
    for (int i = 0; i < 3; i++)
        *(uint32_t*)(dst + i * 4) = pk[i];

    s += __shfl_xor_sync(0xffffffffu, s, 1);
    s += __shfl_xor_sync(0xffffffffu, s, 2);
    s += __shfl_xor_sync(0xffffffffu, s, 4);
    s += __shfl_xor_sync(0xffffffffu, s, 8);
    if (part == 0) g_sq[row] = s;
}

// ---------------------------------------------------------------------------
// pair kernel: 128x64 tile per 256-thread CTA, 8 warps (4x2), each warp
// 32x32 via m16n8k32 e4m3/f16 MMA. Compact 1-D triangular grid. 51-reg cap.
// ---------------------------------------------------------------------------
__global__ void __launch_bounds__(256, 5) pair_kernel() {
    extern __shared__ char smem[];
    const uint32_t sbase = smem_u32(smem);

    // decode t -> (bi, cj): tiles for row bi start at S(bi) = bi*(129-bi).
    // float sqrt estimate + exact int correction (regs: no doubles).
    const int t = blockIdx.x;
    int bi = (int)((129.f - sqrtf((float)(16641 - 4 * t))) * 0.5f);
    if (bi < 0) bi = 0;
    if (bi > NTB - 1) bi = NTB - 1;
    while ((bi + 1) * (129 - (bi + 1)) <= t) bi++;
    while (bi * (129 - bi) > t) bi--;
    const int cj = 2 * bi + (t - bi * (129 - bi));
    const bool diag = ((cj >> 1) == bi);   // tile contains diagonal cells

    const int tid  = threadIdx.x;
    const int lane = tid & 31;
    const int wid  = tid >> 5;
    const int wm   = wid >> 1;   // 0..3 : 32-row slab
    const int wn   = wid & 1;    // 0..1 : 32-col slab

    // ---- stage via cp.async (incremental index math) ----
    const uint8_t* Asrc = g_zb + (size_t)bi * TMR * DIM;
    const uint8_t* Bsrc = g_zb + (size_t)cj * TMC * DIM;
    {
        int m = tid / 12, ch = tid - m * 12;   // idx = tid
        int m2 = m, ch2 = ch;
        #pragma unroll
        for (int r = 0; r < 6; r++) {          // A: 1536 chunks
            CPASYNC16(sbase + OFF_A + m * RSTRIDE + ch * 16,
                      Asrc + (size_t)m * DIM + ch * 16);
            m += 21; ch += 4;                  // += 256 = 21*12 + 4
            if (ch >= 12) { ch -= 12; m += 1; }
        }
        if (!diag) {
            #pragma unroll
            for (int r = 0; r < 3; r++) {      // B: 768 chunks
                CPASYNC16(sbase + OFF_B + m2 * RSTRIDE + ch2 * 16,
                          Bsrc + (size_t)m2 * DIM + ch2 * 16);
                m2 += 21; ch2 += 4;
                if (ch2 >= 12) { ch2 -= 12; m2 += 1; }
            }
        }
    }
    asm volatile("cp.async.commit_group;" ::: "memory");

    // tile-level min norms for the screen (warps 0/1, via __ldg; written
    // BEFORE the single barrier so the epilogue can read them sync-free)
    {
        float* red = (float*)(smem + OFF_RED);
        if (wid == 0) {
            float v = fminf(fminf(__ldg(&g_sq[bi * TMR + lane]),
                                  __ldg(&g_sq[bi * TMR + lane + 32])),
                            fminf(__ldg(&g_sq[bi * TMR + lane + 64]),
                                  __ldg(&g_sq[bi * TMR + lane + 96])));
            #pragma unroll
            for (int o = 16; o; o >>= 1) v = fminf(v, __shfl_xor_sync(0xffffffffu, v, o));
            if (lane == 0) red[8] = v;
        } else if (wid == 1) {
            float v = fminf(__ldg(&g_sq[cj * TMC + lane]),
                            __ldg(&g_sq[cj * TMC + lane + 32]));
            #pragma unroll
            for (int o = 16; o; o >>= 1) v = fminf(v, __shfl_xor_sync(0xffffffffu, v, o));
            if (lane == 0) red[9] = v;
        }
    }
    asm volatile("cp.async.wait_group 0;" ::: "memory");
    __syncthreads();

    // per-lane ldmatrix bases
    const uint32_t aBase = sbase + OFF_A
        + (uint32_t)(wm * 32 + (lane & 15)) * RSTRIDE + ((lane >> 4) << 4);
    const uint32_t bOff = diag ? (OFF_A + (uint32_t)(cj & 1) * 64 * RSTRIDE) : OFF_B;
    const uint32_t bBase = sbase + bOff
        + (uint32_t)(wn * 32 + ((lane & 7) | ((lane >> 4) << 3))) * RSTRIDE
        + (((lane >> 3) & 1) << 4);

    uint32_t acc[2][4][2];   // [mt][ntk][row-half], f16x2 each (16 regs)
    #pragma unroll
    for (int i = 0; i < 2; i++)
        #pragma unroll
        for (int j = 0; j < 4; j++) { acc[i][j][0] = 0u; acc[i][j][1] = 0u; }

    #pragma unroll
    for (int ks = 0; ks < NKS; ks++) {
        uint32_t a[2][4], b[2][4];
        #pragma unroll
        for (int mt = 0; mt < 2; mt++)
            LDSM4(a[mt], aBase + (uint32_t)(mt * 16) * RSTRIDE + ks * 32);
        #pragma unroll
        for (int n2 = 0; n2 < 2; n2++)
            LDSM4(b[n2], bBase + (uint32_t)(n2 * 16) * RSTRIDE + ks * 32);
        #pragma unroll
        for (int mt = 0; mt < 2; mt++)
            #pragma unroll
            for (int ntk = 0; ntk < 4; ntk++) {
                const uint32_t* bf = b[ntk >> 1];
                if (ntk & 1) MMAF8H(acc[mt][ntk], a[mt], bf[2], bf[3]);
                else         MMAF8H(acc[mt][ntk], a[mt], bf[0], bf[1]);
            }
    }

    // ---- epilogue: tile-min screen (HMAX2), then (rarely) exp ----
    float* red = (float*)(smem + OFF_RED);
    const int cls = (cj < 64) ? 0 : ((bi >= 32) ? 2 : 1);   // 0=XX,1=XY,2=YY

    __half2 hm = *(const __half2*)&acc[0][0][0];
    #pragma unroll
    for (int mt = 0; mt < 2; mt++)
        #pragma unroll
        for (int ntk = 0; ntk < 4; ntk++)
            #pragma unroll
            for (int rh = 0; rh < 2; rh++)
                hm = __hmax2(hm, *(const __half2*)&acc[mt][ntk][rh]);
    float accmax = fmaxf(__low2float(hm), __high2float(hm));
    const bool hot = (2.f * accmax - red[8] - red[9]) > -215.f;

    float sum = 0.f;
    if (__ballot_sync(0xffffffffu, hot)) {
        const float wgt = (cls == 1) ? 1.f : 2.f;
        const int g  = lane >> 2;
        const int t4 = lane & 3;
        #pragma unroll
        for (int mt = 0; mt < 2; mt++) {
            #pragma unroll
            for (int ntk = 0; ntk < 4; ntk++) {
                #pragma unroll
                for (int rh = 0; rh < 2; rh++) {
                    float2 v2 = __half22float2(*(const __half2*)&acc[mt][ntk][rh]);
                    float siv = __ldg(&g_sq[bi * TMR + wm * 32 + mt * 16 + g + rh * 8]);
                    #pragma unroll
                    for (int cl = 0; cl < 2; cl++) {
                        const int gi = bi * TMR + wm * 32 + mt * 16 + g + rh * 8;
                        const int gj = cj * TMC + wn * 32 + ntk * 8 + 2 * t4 + cl;
                        float sjv = __ldg(&g_sq[gj]);
                        float vv = cl ? v2.y : v2.x;
                        float d2 = fmaxf(siv + sjv - 2.f * vv, 0.f);
                        if (diag && gi >= gj) continue;   // diagonal analytic
                        if (d2 < 174.f) sum += wgt * __expf(-0.5f * d2);
                    }
                }
            }
        }
    }
    if (diag && tid == 0) sum += 64.f;   // exact diagonal cells in this tile

    #pragma unroll
    for (int o = 16; o; o >>= 1) sum += __shfl_xor_sync(0xffffffffu, sum, o);
    if (lane == 0) red[wid] = sum;
    __syncthreads();
    if (tid == 0) {
        float tot = 0.f;
        #pragma unroll
        for (int w = 0; w < 8; w++) tot += red[w];
        atomicAdd(&g_sums[cls], (double)tot);
    }
}

// ---------------------------------------------------------------------------
// finalize
// ---------------------------------------------------------------------------
__global__ void fin_kernel(const float* __restrict__ avg_step,
                           float* __restrict__ out, int out_size) {
    const double inv = 1.0 / ((double)NROW * (double)NROW);
    float xx = (float)(g_sums[0] * inv);
    float xy = (float)(g_sums[1] * inv);
    float yy = (float)(g_sums[2] * inv);
    float mmd  = xx + yy - 2.0f * xy;
    float a    = avg_step[0];
    float loss = mmd + (fmaxf(1.0f, a) - 1.0f) * 0.002f;
    out[0] = loss;
    if (out_size > 1) out[1] = mmd;
}

extern "C" void kernel_launch(void* const* d_in, const int* in_sizes, int n_in,
                              void* d_out, int out_size) {
    const float* x  = (const float*)d_in[0];
    const float* y  = (const float*)d_in[1];
    const float* av = (const float*)d_in[2];
    float* out = (float*)d_out;

    prep_kernel<<<1024, 128>>>(x, y);
    cudaFuncSetAttribute(pair_kernel,
                         cudaFuncAttributeMaxDynamicSharedMemorySize, SMEM_TOTAL);
    pair_kernel<<<NTILE, 256, SMEM_TOTAL>>>();
    fin_kernel<<<1, 1>>>(av, out, out_size);
}

// round 17
// speedup vs baseline: 1.3204x; 1.2677x over previous
#include <cuda_runtime.h>
#include <cuda_bf16.h>
#include <cuda_fp16.h>
#include <math.h>
#include <stdint.h>

// MMD via fp8(e4m3) mma.sync Gram, f16 accumulators.
// R17: finer scheduling granularity. R14 (best, 51.7us) = 256thr/128x64 tiles,
// occ 4 -> 7.03 waves -> 8 tile-times with a 3%-full last wave. Now 128thr CTAs
// on 64x64 tiles: same 32 warps/SM (occ 8, 64-reg cap that R14 proved fits),
// 8256 tiles / 1184 slots = 6.97 -> 7 waves. Per-warp work unchanged.
// exp(-d2/2) underflows to 0 in fp32 for d2>174.67; min off-diagonal d2 ~200,
// so fragments are screened; diagonal emitted analytically (exactly 1.0).

#define NROW 4096
#define DIM  192
#define ZROW 8192
#define TS   64                    // tile size (rows = cols)
#define NTB2 128                   // 8192/64 tiles per dim
#define NTILE 8256                 // 128*129/2
#define NKS  6                     // K steps of 32 fp8

#define RSTRIDE 208                // 192B row + 16B pad (conflict-free ldmatrix)
#define OFF_A   0
#define OFF_B   (TS * RSTRIDE)             // 13312
#define OFF_SQI (2 * TS * RSTRIDE)         // 26624 (64 floats)
#define OFF_SQJ (OFF_SQI + 256)            // (64 floats)
#define OFF_RED (OFF_SQJ + 256)            // 4 warp sums
#define SMEM_TOTAL (OFF_RED + 64)          // 27200

__device__ double  g_sums[3];               // XX, XY, YY weighted sums
__device__ float   g_sq[ZROW];              // fp32 squared norms
__device__ uint8_t g_zb[ZROW * DIM];        // e4m3 copy of Z

__device__ __forceinline__ uint32_t smem_u32(const void* p) {
    return (uint32_t)__cvta_generic_to_shared((void*)p);
}

#define LDSM4(r, addr)                                                         \
    asm volatile("ldmatrix.sync.aligned.m8n8.x4.shared.b16 "                   \
                 "{%0, %1, %2, %3}, [%4];"                                     \
                 : "=r"((r)[0]), "=r"((r)[1]), "=r"((r)[2]), "=r"((r)[3])      \
                 : "r"(addr))

#define MMAF8H(c, a, b0, b1)                                                   \
    asm volatile("mma.sync.aligned.m16n8k32.row.col.f16.e4m3.e4m3.f16 "        \
                 "{%0, %1}, {%2, %3, %4, %5}, {%6, %7}, {%0, %1};"             \
                 : "+r"((c)[0]), "+r"((c)[1])                                  \
                 : "r"((a)[0]), "r"((a)[1]), "r"((a)[2]), "r"((a)[3]),         \
                   "r"(b0), "r"(b1))

#define CPASYNC16(dst, src)                                                    \
    asm volatile("cp.async.cg.shared.global [%0], [%1], 16;"                   \
                 :: "r"(dst), "l"(src))

// ---------------------------------------------------------------------------
// prep: sixteenth-row per thread (3 independent float4 loads), 1024 CTAs x 128
// ---------------------------------------------------------------------------
__global__ void __launch_bounds__(128) prep_kernel(const float* __restrict__ x,
                                                   const float* __restrict__ y) {
    if (blockIdx.x == 0 && threadIdx.x < 3) g_sums[threadIdx.x] = 0.0;
    const int gid  = blockIdx.x * 128 + threadIdx.x;   // 131072 threads
    const int row  = gid >> 4;
    const int part = gid & 15;                         // 12 floats each
    const float* p = ((row < NROW) ? (x + (size_t)row * DIM)
                                   : (y + (size_t)(row - NROW) * DIM)) + part * 12;

    float4 v[3];
    #pragma unroll
    for (int i = 0; i < 3; i++) v[i] = *(const float4*)(p + i * 4);

    float s = 0.f;
    uint32_t pk[3];
    #pragma unroll
    for (int i = 0; i < 3; i++) {
        s = fmaf(v[i].x, v[i].x, s); s = fmaf(v[i].y, v[i].y, s);
        s = fmaf(v[i].z, v[i].z, s); s = fmaf(v[i].w, v[i].w, s);
        unsigned short lo, hi;
        asm("cvt.rn.satfinite.e4m3x2.f32 %0, %1, %2;" : "=h"(lo) : "f"(v[i].y), "f"(v[i].x));
        asm("cvt.rn.satfinite.e4m3x2.f32 %0, %1, %2;" : "=h"(hi) : "f"(v[i].w), "f"(v[i].z));
        pk[i] = (uint32_t)lo | ((uint32_t)hi << 16);
    }
    uint8_t* dst = g_zb + (size_t)row * DIM + part * 12;   // 4B aligned
    #pragma unroll
    for (int i = 0; i < 3; i++)
        *(uint32_t*)(dst + i * 4) = pk[i];

    s += __shfl_xor_sync(0xffffffffu, s, 1);
    s += __shfl_xor_sync(0xffffffffu, s, 2);
    s += __shfl_xor_sync(0xffffffffu, s, 4);
    s += __shfl_xor_sync(0xffffffffu, s, 8);
    if (part == 0) g_sq[row] = s;
}

// ---------------------------------------------------------------------------
// pair kernel: 64x64 tile per 128-thread CTA, 4 warps (2x2), each warp
// 32x32 via m16n8k32 e4m3/f16 MMA. Compact 1-D triangular grid. occ 8.
// ---------------------------------------------------------------------------
__global__ void __launch_bounds__(128, 8) pair_kernel() {
    extern __shared__ char smem[];
    const uint32_t sbase = smem_u32(smem);

    // decode t -> (ri, cu), cu >= ri: tiles for row ri start at
    // S(ri) = ri*NTB2 - ri*(ri-1)/2
    const int t = blockIdx.x;
    int ri = (int)((257.f - sqrtf((float)(66049 - 8 * t))) * 0.5f);
    if (ri < 0) ri = 0;
    if (ri > NTB2 - 1) ri = NTB2 - 1;
    #define TRIS(i) ((i) * NTB2 - ((i) * ((i) - 1)) / 2)
    while (TRIS(ri + 1) <= t) ri++;
    while (TRIS(ri) > t) ri--;
    const int cu = ri + (t - TRIS(ri));
    #undef TRIS
    const bool diag = (cu == ri);

    const int tid  = threadIdx.x;
    const int lane = tid & 31;
    const int wid  = tid >> 5;
    const int wm   = wid >> 1;   // 0..1 : 32-row slab
    const int wn   = wid & 1;    // 0..1 : 32-col slab

    // ---- stage via cp.async: 64 rows x 12 chunks per operand ----
    const uint8_t* Asrc = g_zb + (size_t)ri * TS * DIM;
    const uint8_t* Bsrc = g_zb + (size_t)cu * TS * DIM;
    {
        int m = tid / 12, ch = tid - (tid / 12) * 12;
        int m2 = m, ch2 = ch;
        #pragma unroll
        for (int r = 0; r < 6; r++) {          // A: 768 chunks
            CPASYNC16(sbase + OFF_A + m * RSTRIDE + ch * 16,
                      Asrc + (size_t)m * DIM + ch * 16);
            m += 10; ch += 8;                  // += 128 = 10*12 + 8
            if (ch >= 12) { ch -= 12; m += 1; }
        }
        if (!diag) {
            #pragma unroll
            for (int r = 0; r < 6; r++) {      // B: 768 chunks
                CPASYNC16(sbase + OFF_B + m2 * RSTRIDE + ch2 * 16,
                          Bsrc + (size_t)m2 * DIM + ch2 * 16);
                m2 += 10; ch2 += 8;
                if (ch2 >= 12) { ch2 -= 12; m2 += 1; }
            }
        }
    }
    asm volatile("cp.async.commit_group;" ::: "memory");
    if (tid < TS) ((float*)(smem + OFF_SQI))[tid] = g_sq[ri * TS + tid];
    else ((float*)(smem + OFF_SQJ))[tid - TS] = g_sq[cu * TS + tid - TS];
    asm volatile("cp.async.wait_group 0;" ::: "memory");
    __syncthreads();

    // per-lane ldmatrix bases
    const uint32_t aBase = sbase + OFF_A
        + (uint32_t)(wm * 32 + (lane & 15)) * RSTRIDE + ((lane >> 4) << 4);
    const uint32_t bBase = sbase + (diag ? OFF_A : OFF_B)
        + (uint32_t)(wn * 32 + ((lane & 7) | ((lane >> 4) << 3))) * RSTRIDE
        + (((lane >> 3) & 1) << 4);

    uint32_t acc[2][4][2];   // [mt][ntk][row-half], f16x2 each (16 regs)
    #pragma unroll
    for (int i = 0; i < 2; i++)
        #pragma unroll
        for (int j = 0; j < 4; j++) { acc[i][j][0] = 0u; acc[i][j][1] = 0u; }

    #pragma unroll
    for (int ks = 0; ks < NKS; ks++) {
        uint32_t a[2][4], b[2][4];
        #pragma unroll
        for (int mt = 0; mt < 2; mt++)
            LDSM4(a[mt], aBase + (uint32_t)(mt * 16) * RSTRIDE + ks * 32);
        #pragma unroll
        for (int n2 = 0; n2 < 2; n2++)
            LDSM4(b[n2], bBase + (uint32_t)(n2 * 16) * RSTRIDE + ks * 32);
        #pragma unroll
        for (int mt = 0; mt < 2; mt++)
            #pragma unroll
            for (int ntk = 0; ntk < 4; ntk++) {
                const uint32_t* bf = b[ntk >> 1];
                if (ntk & 1) MMAF8H(acc[mt][ntk], a[mt], bf[2], bf[3]);
                else         MMAF8H(acc[mt][ntk], a[mt], bf[0], bf[1]);
            }
    }

    // ---- epilogue: screen (HMAX2), then (rarely) exp ----
    const float* sqi = (const float*)(smem + OFF_SQI);
    const float* sqj = (const float*)(smem + OFF_SQJ);
    const int g  = lane >> 2;
    const int t4 = lane & 3;
    const int cls = (cu < TS) ? 0 : ((ri >= TS) ? 2 : 1);   // 0=XX,1=XY,2=YY
    const float wgt = (cls == 1) ? 1.f : 2.f;

    float si[2][2], sj[4][2];
    #pragma unroll
    for (int mt = 0; mt < 2; mt++) {
        si[mt][0] = sqi[wm * 32 + mt * 16 + g];
        si[mt][1] = sqi[wm * 32 + mt * 16 + g + 8];
    }
    #pragma unroll
    for (int ntk = 0; ntk < 4; ntk++) {
        sj[ntk][0] = sqj[wn * 32 + ntk * 8 + 2 * t4];
        sj[ntk][1] = sqj[wn * 32 + ntk * 8 + 2 * t4 + 1];
    }

    __half2 hm = *(const __half2*)&acc[0][0][0];
    #pragma unroll
    for (int mt = 0; mt < 2; mt++)
        #pragma unroll
        for (int ntk = 0; ntk < 4; ntk++)
            #pragma unroll
            for (int rh = 0; rh < 2; rh++)
                hm = __hmax2(hm, *(const __half2*)&acc[mt][ntk][rh]);
    float accmax = fmaxf(__low2float(hm), __high2float(hm));
    float minsi = fminf(fminf(si[0][0], si[0][1]), fminf(si[1][0], si[1][1]));
    float minsj = fminf(fminf(fminf(sj[0][0], sj[0][1]), fminf(sj[1][0], sj[1][1])),
                        fminf(fminf(sj[2][0], sj[2][1]), fminf(sj[3][0], sj[3][1])));
    const bool hot = (2.f * accmax - minsi - minsj) > -215.f;

    float sum = 0.f;
    if (__ballot_sync(0xffffffffu, hot)) {
        #pragma unroll
        for (int mt = 0; mt < 2; mt++) {
            #pragma unroll
            for (int ntk = 0; ntk < 4; ntk++) {
                #pragma unroll
                for (int rh = 0; rh < 2; rh++) {
                    float2 v2 = __half22float2(*(const __half2*)&acc[mt][ntk][rh]);
                    #pragma unroll
                    for (int cl = 0; cl < 2; cl++) {
                        const int gi = ri * TS + wm * 32 + mt * 16 + g + rh * 8;
                        const int gj = cu * TS + wn * 32 + ntk * 8 + 2 * t4 + cl;
                        float vv = cl ? v2.y : v2.x;
                        float d2 = fmaxf(si[mt][rh] + sj[ntk][cl] - 2.f * vv, 0.f);
                        if (diag && gi >= gj) continue;   // diagonal analytic
                        if (d2 < 174.f) sum += wgt * __expf(-0.5f * d2);
                    }
                }
            }
        }
    }
    if (diag && tid == 0) sum += 64.f;   // exact diagonal cells in this tile

    #pragma unroll
    for (int o = 16; o; o >>= 1) sum += __shfl_xor_sync(0xffffffffu, sum, o);
    float* red = (float*)(smem + OFF_RED);
    if (lane == 0) red[wid] = sum;
    __syncthreads();
    if (tid == 0) {
        atomicAdd(&g_sums[cls], (double)(red[0] + red[1] + red[2] + red[3]));
    }
}

// ---------------------------------------------------------------------------
// finalize
// ---------------------------------------------------------------------------
__global__ void fin_kernel(const float* __restrict__ avg_step,
                           float* __restrict__ out, int out_size) {
    const double inv = 1.0 / ((double)NROW * (double)NROW);
    float xx = (float)(g_sums[0] * inv);
    float xy = (float)(g_sums[1] * inv);
    float yy = (float)(g_sums[2] * inv);
    float mmd  = xx + yy - 2.0f * xy;
    float a    = avg_step[0];
    float loss = mmd + (fmaxf(1.0f, a) - 1.0f) * 0.002f;
    out[0] = loss;
    if (out_size > 1) out[1] = mmd;
}

extern "C" void kernel_launch(void* const* d_in, const int* in_sizes, int n_in,
                              void* d_out, int out_size) {
    const float* x  = (const float*)d_in[0];
    const float* y  = (const float*)d_in[1];
    const float* av = (const float*)d_in[2];
    float* out = (float*)d_out;

    prep_kernel<<<1024, 128>>>(x, y);
    cudaFuncSetAttribute(pair_kernel,
                         cudaFuncAttributeMaxDynamicSharedMemorySize, SMEM_TOTAL);
    cudaFuncSetAttribute(pair_kernel,
                         cudaFuncAttributePreferredSharedMemoryCarveout, 100);
    pair_kernel<<<NTILE, 128, SMEM_TOTAL>>>();
    fin_kernel<<<1, 1>>>(av, out, out_size);
}